// round 5
// baseline (speedup 1.0000x reference)
#include <cuda_runtime.h>
#include <cuda_fp16.h>
#include <math.h>

#define NN 50000
#define NE 800000
#define FD 256
#define HEADS 4
#define CH 64

// ---- scratch (static device globals: no runtime allocation) ----
__device__ __half g_h[(size_t)NN * FD];    // GEMM output (fp16: halves gather traffic)
__device__ float  g_y[(size_t)NN * FD];    // layer-1 output (GEMM input of layer 2)
__device__ float  g_asrc[NN * HEADS];
__device__ float  g_adst[NN * HEADS];
__device__ int    g_cnt[NN];
__device__ int    g_off[NN + 1];
__device__ int    g_col[NE];               // CSR: src per position

__device__ __forceinline__ float lrelu(float x) { return fmaxf(x, 0.2f * x); }

__device__ __forceinline__ unsigned f2tf(float f) {
    unsigned u;
    asm("cvt.rna.tf32.f32 %0, %1;" : "=r"(u) : "f"(f));
    return u;
}

__device__ __forceinline__ void mma_tf32(float* c, const unsigned* a, const unsigned* b) {
    asm volatile(
        "mma.sync.aligned.m16n8k8.row.col.f32.tf32.tf32.f32 "
        "{%0,%1,%2,%3},{%4,%5,%6,%7},{%8,%9},{%0,%1,%2,%3};"
        : "+f"(c[0]), "+f"(c[1]), "+f"(c[2]), "+f"(c[3])
        : "r"(a[0]), "r"(a[1]), "r"(a[2]), "r"(a[3]), "r"(b[0]), "r"(b[1]));
}

// ---------------- CSR build ----------------
__global__ void k_zero_cnt() {
    int i = blockIdx.x * blockDim.x + threadIdx.x;
    if (i < NN) g_cnt[i] = 0;
}

__global__ void k_hist(const int* __restrict__ dst) {
    int e = blockIdx.x * blockDim.x + threadIdx.x;
    if (e < NE) atomicAdd(&g_cnt[dst[e]], 1);
}

// single-block shuffle scan: 1024 threads x 49 contiguous counts each.
__global__ void k_scan() {
    const int T = 1024, PER = (NN + T - 1) / T;   // 49
    __shared__ int wsum[32];
    const int t = threadIdx.x, lane = t & 31, wid = t >> 5;
    const int base = t * PER;

    int sum = 0;
    for (int i = 0; i < PER; i++) {
        int idx = base + i;
        if (idx < NN) sum += g_cnt[idx];
    }
    int v = sum;
#pragma unroll
    for (int o = 1; o < 32; o <<= 1) {
        int n = __shfl_up_sync(0xffffffffu, v, o);
        if (lane >= o) v += n;
    }
    if (lane == 31) wsum[wid] = v;
    __syncthreads();
    if (wid == 0) {
        int wv = wsum[lane];
#pragma unroll
        for (int o = 1; o < 32; o <<= 1) {
            int n = __shfl_up_sync(0xffffffffu, wv, o);
            if (lane >= o) wv += n;
        }
        wsum[lane] = wv;
    }
    __syncthreads();
    int run = v - sum + (wid > 0 ? wsum[wid - 1] : 0);   // exclusive prefix
    for (int i = 0; i < PER; i++) {
        int idx = base + i;
        if (idx < NN) {
            int c = g_cnt[idx];
            g_off[idx] = run;
            run += c;
            g_cnt[idx] = 0;
        }
    }
    if (t == 0) g_off[NN] = wsum[31];
}

__global__ void k_scatter(const int* __restrict__ src, const int* __restrict__ dst) {
    int e = blockIdx.x * blockDim.x + threadIdx.x;
    if (e < NE) {
        int d = dst[e];
        int pos = g_off[d] + atomicAdd(&g_cnt[d], 1);
        g_col[pos] = src[e];
    }
}

// ---------------- tf32 tensor-core GEMM + fused attention-logit epilogue ----
// Block tile 64(M) x 256(N), BK=16, 8 warps (4 wm x 2 wn), warp tile 16x128.
// TWO-STAGE smem double buffer: one __syncthreads per K-chunk; LDG of chunk
// k+1 overlaps compute of chunk k. h is stored as fp16.
__global__ void __launch_bounds__(256) k_gemm_att(
    const float* __restrict__ Ain,          // nullptr -> use g_y
    const float* __restrict__ W,
    const float* __restrict__ att_s,
    const float* __restrict__ att_d)
{
    const float* A = Ain ? Ain : g_y;
    __shared__ unsigned sA[2][64][20];
    __shared__ unsigned sB[2][16][264];

    const int t    = threadIdx.x;
    const int lane = t & 31;
    const int wid  = t >> 5;
    const int gid  = lane >> 2, tig = lane & 3;
    const int wm   = wid & 3,   wn  = wid >> 2;
    const int row0 = blockIdx.x * 64;

    float acc[16][4] = {};

    const int ar = t >> 2, ac = (t & 3) * 4;
    const int br = t >> 4, bc = (t & 15) * 4;
    const bool arow_ok = (row0 + ar) < NN;
    const float* aptr = A + (size_t)(row0 + ar) * FD + ac;
    const float* bptr = W + (size_t)br * FD + bc;

    float4 aval = make_float4(0.f, 0.f, 0.f, 0.f);
    float4 bval[4];
    if (arow_ok) aval = *(const float4*)aptr;
#pragma unroll
    for (int sub = 0; sub < 4; sub++)
        bval[sub] = *(const float4*)(bptr + sub * 64);

    int st = 0;
    for (int k0 = 0; k0 < FD; k0 += 16) {
        *(uint4*)&sA[st][ar][ac] = make_uint4(f2tf(aval.x), f2tf(aval.y),
                                              f2tf(aval.z), f2tf(aval.w));
#pragma unroll
        for (int sub = 0; sub < 4; sub++)
            *(uint4*)&sB[st][br][bc + sub * 64] =
                make_uint4(f2tf(bval[sub].x), f2tf(bval[sub].y),
                           f2tf(bval[sub].z), f2tf(bval[sub].w));
        __syncthreads();

        if (k0 + 16 < FD) {                 // prefetch next chunk into regs
            aval = make_float4(0.f, 0.f, 0.f, 0.f);
            if (arow_ok) aval = *(const float4*)(aptr + k0 + 16);
#pragma unroll
            for (int sub = 0; sub < 4; sub++)
                bval[sub] = *(const float4*)(bptr + (size_t)(k0 + 16) * FD + sub * 64);
        }

#pragma unroll
        for (int kk = 0; kk < 16; kk += 8) {
            unsigned af[4];
            const int r = wm * 16 + gid;
            af[0] = sA[st][r    ][kk + tig];
            af[1] = sA[st][r + 8][kk + tig];
            af[2] = sA[st][r    ][kk + tig + 4];
            af[3] = sA[st][r + 8][kk + tig + 4];
            unsigned bf[16][2];
#pragma unroll
            for (int tn = 0; tn < 16; tn++) {
                const int c = wn * 128 + tn * 8 + gid;
                bf[tn][0] = sB[st][kk + tig    ][c];
                bf[tn][1] = sB[st][kk + tig + 4][c];
            }
#pragma unroll
            for (int tn = 0; tn < 16; tn++)
                mma_tf32(acc[tn], af, bf[tn]);
        }
        st ^= 1;                            // no second sync: other buffer next
    }

    // ---- epilogue: store h (fp16), fused per-head attention dots ----
#pragma unroll
    for (int rh = 0; rh < 2; rh++) {
        const int r = row0 + wm * 16 + rh * 8 + gid;
        const bool rok = r < NN;
        if (rok) {
#pragma unroll
            for (int tn = 0; tn < 16; tn++) {
                const int c = wn * 128 + tn * 8 + 2 * tig;
                *(__half2*)(g_h + (size_t)r * FD + c) =
                    __floats2half2_rn(acc[tn][rh * 2], acc[tn][rh * 2 + 1]);
            }
        }
#pragma unroll
        for (int h2 = 0; h2 < 2; h2++) {
            float s_ = 0.f, d_ = 0.f;
#pragma unroll
            for (int tn8 = 0; tn8 < 8; tn8++) {
                const int tn = h2 * 8 + tn8;
                const int c = wn * 128 + tn * 8 + 2 * tig;
                const float v0 = acc[tn][rh * 2], v1 = acc[tn][rh * 2 + 1];
                s_ = fmaf(v0, att_s[c], fmaf(v1, att_s[c + 1], s_));
                d_ = fmaf(v0, att_d[c], fmaf(v1, att_d[c + 1], d_));
            }
            s_ += __shfl_xor_sync(0xffffffffu, s_, 1);
            s_ += __shfl_xor_sync(0xffffffffu, s_, 2);
            d_ += __shfl_xor_sync(0xffffffffu, d_, 1);
            d_ += __shfl_xor_sync(0xffffffffu, d_, 2);
            if (tig == 0 && rok) {
                const int head = wn * 2 + h2;
                g_asrc[r * HEADS + head] = s_;
                g_adst[r * HEADS + head] = d_;
            }
        }
    }
}

// ---------------- per-dst-node aggregation: one warp per node ----------------
// Single pass, max-free softmax (logits O(5): exp cannot overflow).
// fp16 h rows: 1 LDG.128 per lane per edge. lane -> 8 channels, head = lane/8.
__global__ void __launch_bounds__(256) k_aggregate(
    const float* __restrict__ bias,
    float* __restrict__ outp)               // nullptr -> g_y
{
    const int w = (blockIdx.x * blockDim.x + threadIdx.x) >> 5;
    const int lane = threadIdx.x & 31;
    if (w >= NN) return;
    const int hd = lane >> 3;
    const float ad = g_adst[w * HEADS + hd];
    const int beg = g_off[w], end = g_off[w + 1];

    // self loop
    float wt = __expf(lrelu(g_asrc[w * HEADS + hd] + ad));
    float denom = wt;
    float a0, a1, a2, a3, a4, a5, a6, a7;
    {
        const uint4 raw = *(const uint4*)(g_h + (size_t)w * FD + lane * 8);
        const __half2* hp = (const __half2*)&raw;
        const float2 f0 = __half22float2(hp[0]), f1 = __half22float2(hp[1]);
        const float2 f2 = __half22float2(hp[2]), f3 = __half22float2(hp[3]);
        a0 = wt * f0.x; a1 = wt * f0.y; a2 = wt * f1.x; a3 = wt * f1.y;
        a4 = wt * f2.x; a5 = wt * f2.y; a6 = wt * f3.x; a7 = wt * f3.y;
    }

    int k = beg;
    for (; k + 2 <= end; k += 2) {
        const int s0 = g_col[k], s1 = g_col[k + 1];
        const float e0 = g_asrc[s0 * HEADS + hd] + ad;
        const float e1 = g_asrc[s1 * HEADS + hd] + ad;
        const uint4 r0 = *(const uint4*)(g_h + (size_t)s0 * FD + lane * 8);
        const uint4 r1 = *(const uint4*)(g_h + (size_t)s1 * FD + lane * 8);
        const float w0 = __expf(lrelu(e0));
        const float w1 = __expf(lrelu(e1));
        denom += w0 + w1;
        const __half2* p0 = (const __half2*)&r0;
        const __half2* p1 = (const __half2*)&r1;
        const float2 x00 = __half22float2(p0[0]), x01 = __half22float2(p0[1]);
        const float2 x02 = __half22float2(p0[2]), x03 = __half22float2(p0[3]);
        const float2 x10 = __half22float2(p1[0]), x11 = __half22float2(p1[1]);
        const float2 x12 = __half22float2(p1[2]), x13 = __half22float2(p1[3]);
        a0 = fmaf(w0, x00.x, fmaf(w1, x10.x, a0));
        a1 = fmaf(w0, x00.y, fmaf(w1, x10.y, a1));
        a2 = fmaf(w0, x01.x, fmaf(w1, x11.x, a2));
        a3 = fmaf(w0, x01.y, fmaf(w1, x11.y, a3));
        a4 = fmaf(w0, x02.x, fmaf(w1, x12.x, a4));
        a5 = fmaf(w0, x02.y, fmaf(w1, x12.y, a5));
        a6 = fmaf(w0, x03.x, fmaf(w1, x13.x, a6));
        a7 = fmaf(w0, x03.y, fmaf(w1, x13.y, a7));
    }
    if (k < end) {
        const int s = g_col[k];
        const float wt1 = __expf(lrelu(g_asrc[s * HEADS + hd] + ad));
        denom += wt1;
        const uint4 raw = *(const uint4*)(g_h + (size_t)s * FD + lane * 8);
        const __half2* hp = (const __half2*)&raw;
        const float2 f0 = __half22float2(hp[0]), f1 = __half22float2(hp[1]);
        const float2 f2 = __half22float2(hp[2]), f3 = __half22float2(hp[3]);
        a0 = fmaf(wt1, f0.x, a0); a1 = fmaf(wt1, f0.y, a1);
        a2 = fmaf(wt1, f1.x, a2); a3 = fmaf(wt1, f1.y, a3);
        a4 = fmaf(wt1, f2.x, a4); a5 = fmaf(wt1, f2.y, a5);
        a6 = fmaf(wt1, f3.x, a6); a7 = fmaf(wt1, f3.y, a7);
    }

    const float inv = 1.0f / (denom + 1e-16f);
    const float* bp = bias + lane * 8;
    float r0 = a0 * inv + bp[0], r1 = a1 * inv + bp[1];
    float r2 = a2 * inv + bp[2], r3 = a3 * inv + bp[3];
    float r4 = a4 * inv + bp[4], r5 = a5 * inv + bp[5];
    float r6 = a6 * inv + bp[6], r7 = a7 * inv + bp[7];
    r0 = r0 > 0.f ? r0 : expm1f(r0);  r1 = r1 > 0.f ? r1 : expm1f(r1);
    r2 = r2 > 0.f ? r2 : expm1f(r2);  r3 = r3 > 0.f ? r3 : expm1f(r3);
    r4 = r4 > 0.f ? r4 : expm1f(r4);  r5 = r5 > 0.f ? r5 : expm1f(r5);
    r6 = r6 > 0.f ? r6 : expm1f(r6);  r7 = r7 > 0.f ? r7 : expm1f(r7);

    float* op = (outp ? outp : g_y) + (size_t)w * FD + lane * 8;
    *(float4*)op       = make_float4(r0, r1, r2, r3);
    *((float4*)op + 1) = make_float4(r4, r5, r6, r7);
}

// ---------------- launch ----------------
extern "C" void kernel_launch(void* const* d_in, const int* in_sizes, int n_in,
                              void* d_out, int out_size)
{
    const float* x   = (const float*)d_in[0];
    const int*   ei  = (const int*)d_in[1];
    const float* W1  = (const float*)d_in[2];
    const float* as1 = (const float*)d_in[3];
    const float* ad1 = (const float*)d_in[4];
    const float* b1  = (const float*)d_in[5];
    const float* W2  = (const float*)d_in[6];
    const float* as2 = (const float*)d_in[7];
    const float* ad2 = (const float*)d_in[8];
    const float* b2  = (const float*)d_in[9];

    const int* src = ei;            // edge_index row 0
    const int* dst = ei + NE;       // edge_index row 1

    const int ggrid = (NN + 63) / 64;
    const int agrid = (NN * 32 + 255) / 256;

    // CSR build interleaved with layer-1 GEMM so that k_gemm_att lands in
    // the profiled (4th) launch slot. gemm1 has no dependence on the CSR.
    k_zero_cnt<<<(NN + 255) / 256, 256>>>();
    k_hist<<<(NE + 255) / 256, 256>>>(dst);
    k_scan<<<1, 1024>>>();                            // scan + re-zero g_cnt
    k_gemm_att<<<ggrid, 256>>>(x, W1, as1, ad1);      // <- profiled slot
    k_scatter<<<(NE + 255) / 256, 256>>>(src, dst);

    // layer 1 aggregation
    k_aggregate<<<agrid, 256>>>(b1, nullptr);
    // layer 2
    k_gemm_att<<<ggrid, 256>>>(nullptr, W2, as2, ad2);
    k_aggregate<<<agrid, 256>>>(b2, (float*)d_out);
}

// round 6
// speedup vs baseline: 1.5943x; 1.5943x over previous
#include <cuda_runtime.h>
#include <cuda_fp16.h>
#include <math.h>

#define NN 50000
#define NE 800000
#define FD 256
#define HEADS 4
#define CH 64

// ---- scratch (static device globals: no runtime allocation) ----
__device__ __half g_h[(size_t)NN * FD];    // GEMM output (fp16: halves gather traffic)
__device__ float  g_y[(size_t)NN * FD];    // layer-1 output (GEMM input of layer 2)
__device__ float  g_asrc[NN * HEADS];
__device__ float  g_adst[NN * HEADS];
__device__ int    g_cnt[NN];
__device__ int    g_off[NN + 1];
__device__ int    g_col[NE];               // CSR: src per position

__device__ __forceinline__ float lrelu(float x) { return fmaxf(x, 0.2f * x); }

__device__ __forceinline__ unsigned f2tf(float f) {
    unsigned u;
    asm("cvt.rna.tf32.f32 %0, %1;" : "=r"(u) : "f"(f));
    return u;
}

__device__ __forceinline__ void mma_tf32(float* c, const unsigned* a, const unsigned* b) {
    asm volatile(
        "mma.sync.aligned.m16n8k8.row.col.f32.tf32.tf32.f32 "
        "{%0,%1,%2,%3},{%4,%5,%6,%7},{%8,%9},{%0,%1,%2,%3};"
        : "+f"(c[0]), "+f"(c[1]), "+f"(c[2]), "+f"(c[3])
        : "r"(a[0]), "r"(a[1]), "r"(a[2]), "r"(a[3]), "r"(b[0]), "r"(b[1]));
}

// ---------------- CSR build ----------------
__global__ void k_zero_cnt() {
    int i = blockIdx.x * blockDim.x + threadIdx.x;
    if (i < NN) g_cnt[i] = 0;
}

__global__ void k_hist(const int* __restrict__ dst) {
    int e = blockIdx.x * blockDim.x + threadIdx.x;
    if (e < NE) atomicAdd(&g_cnt[dst[e]], 1);
}

// single-block shuffle scan: 1024 threads x 49 contiguous counts each.
__global__ void k_scan() {
    const int T = 1024, PER = (NN + T - 1) / T;   // 49
    __shared__ int wsum[32];
    const int t = threadIdx.x, lane = t & 31, wid = t >> 5;
    const int base = t * PER;

    int sum = 0;
    for (int i = 0; i < PER; i++) {
        int idx = base + i;
        if (idx < NN) sum += g_cnt[idx];
    }
    int v = sum;
#pragma unroll
    for (int o = 1; o < 32; o <<= 1) {
        int n = __shfl_up_sync(0xffffffffu, v, o);
        if (lane >= o) v += n;
    }
    if (lane == 31) wsum[wid] = v;
    __syncthreads();
    if (wid == 0) {
        int wv = wsum[lane];
#pragma unroll
        for (int o = 1; o < 32; o <<= 1) {
            int n = __shfl_up_sync(0xffffffffu, wv, o);
            if (lane >= o) wv += n;
        }
        wsum[lane] = wv;
    }
    __syncthreads();
    int run = v - sum + (wid > 0 ? wsum[wid - 1] : 0);
    for (int i = 0; i < PER; i++) {
        int idx = base + i;
        if (idx < NN) {
            int c = g_cnt[idx];
            g_off[idx] = run;
            run += c;
            g_cnt[idx] = 0;
        }
    }
    if (t == 0) g_off[NN] = wsum[31];
}

__global__ void k_scatter(const int* __restrict__ src, const int* __restrict__ dst) {
    int e = blockIdx.x * blockDim.x + threadIdx.x;
    if (e < NE) {
        int d = dst[e];
        int pos = g_off[d] + atomicAdd(&g_cnt[d], 1);
        g_col[pos] = src[e];
    }
}

// ---------------- tf32 tensor-core GEMM + fused attention-logit epilogue ----
// Block tile 64(M) x 256(N), BK=16, 8 warps = 2 wm x 4 wn; warp tile 32x64.
// Each warp's 64 columns = exactly one head (head = wn): no smem reduction.
// A in FRAGMENT-MAJOR smem layout: one LDS.128 = one full m16k8 A fragment;
// unit addr16 = kkb*128 + wm*64 + tm*32 + gid*4 + tig (phase-conflict-free).
// Mainloop per warp per k8: 2 LDS.128 (A) + 16 LDS.32 (B) + 16 MMA
// (vs 36 scalar LDS before). Double-buffered smem, register prefetch.
__global__ void __launch_bounds__(256) k_gemm_att(
    const float* __restrict__ Ain,          // nullptr -> use g_y
    const float* __restrict__ W,
    const float* __restrict__ att_s,
    const float* __restrict__ att_d)
{
    const float* A = Ain ? Ain : g_y;
    __shared__ unsigned sAf[2][1024];       // fragment-major A (4KB/stage)
    __shared__ unsigned sB[2][16][264];     // [k][n] stride 264 (conflict-free)

    const int t    = threadIdx.x;
    const int lane = t & 31;
    const int wid  = t >> 5;
    const int gid  = lane >> 2, tig = lane & 3;
    const int wm   = wid & 1,   wn  = wid >> 1;   // rows wm*32, cols wn*64
    const int row0 = blockIdx.x * 64;

    float acc[2][8][4] = {};                // [tm][tn][c]

    // ---- staging indices ----
    const int ar = t >> 2, acb = (t & 3) * 4;     // A: row ar, cols acb..acb+3
    const int br = t >> 4, bc = (t & 15) * 4;     // B: row br, 4x 64-strided float4
    const bool arow_ok = (row0 + ar) < NN;
    const float* aptr = A + (size_t)(row0 + ar) * FD + acb;
    const float* bptr = W + (size_t)br * FD + bc;

    // A store word addresses (loop-invariant): fragment-major layout
    int a_st[4];
    {
        const int wm_s = ar >> 5, tm_s = (ar >> 4) & 1;
        const int rh_s = (ar >> 3) & 1, gid_s = ar & 7;
        #pragma unroll
        for (int j = 0; j < 4; j++) {
            const int k = acb + j;
            const int kkb = k >> 3, tg = k & 3, kh = (k >> 2) & 1;
            a_st[j] = (kkb * 128 + wm_s * 64 + tm_s * 32 + gid_s * 4 + tg) * 4
                      + rh_s + 2 * kh;
        }
    }
    // A read word bases (loop-invariant)
    const int a_rd0 = (wm * 64 + gid * 4 + tig) * 4;         // tm=0, kkb=0
    // B read base
    const int b_rd  = tig * 264 + wn * 64 + gid;

    float4 aval = make_float4(0.f, 0.f, 0.f, 0.f);
    float4 bval[4];
    if (arow_ok) aval = *(const float4*)aptr;
#pragma unroll
    for (int sub = 0; sub < 4; sub++)
        bval[sub] = *(const float4*)(bptr + sub * 64);

    int st = 0;
    for (int k0 = 0; k0 < FD; k0 += 16) {
        sAf[st][a_st[0]] = f2tf(aval.x);
        sAf[st][a_st[1]] = f2tf(aval.y);
        sAf[st][a_st[2]] = f2tf(aval.z);
        sAf[st][a_st[3]] = f2tf(aval.w);
#pragma unroll
        for (int sub = 0; sub < 4; sub++)
            *(uint4*)&sB[st][br][bc + sub * 64] =
                make_uint4(f2tf(bval[sub].x), f2tf(bval[sub].y),
                           f2tf(bval[sub].z), f2tf(bval[sub].w));
        __syncthreads();

        if (k0 + 16 < FD) {                 // prefetch next chunk into regs
            aval = make_float4(0.f, 0.f, 0.f, 0.f);
            if (arow_ok) aval = *(const float4*)(aptr + k0 + 16);
#pragma unroll
            for (int sub = 0; sub < 4; sub++)
                bval[sub] = *(const float4*)(bptr + (size_t)(k0 + 16) * FD + sub * 64);
        }

        const unsigned* sa = sAf[st];
        const unsigned* sb = &sB[st][0][0] + b_rd;
#pragma unroll
        for (int kkb = 0; kkb < 2; kkb++) { // kk = kkb*8
            uint4 af0 = *(const uint4*)(sa + kkb * 512 + a_rd0);        // tm=0
            uint4 af1 = *(const uint4*)(sa + kkb * 512 + a_rd0 + 128);  // tm=1
            const unsigned* b0 = sb + kkb * 8 * 264;
            unsigned bf[8][2];
#pragma unroll
            for (int tn = 0; tn < 8; tn++) {
                bf[tn][0] = b0[tn * 8];
                bf[tn][1] = b0[4 * 264 + tn * 8];
            }
#pragma unroll
            for (int tn = 0; tn < 8; tn++) {
                mma_tf32(acc[0][tn], (const unsigned*)&af0, bf[tn]);
                mma_tf32(acc[1][tn], (const unsigned*)&af1, bf[tn]);
            }
        }
        st ^= 1;
    }

    // ---- epilogue: store h (fp16), fused per-head attention dots ----
    const int head = wn;
#pragma unroll
    for (int tm = 0; tm < 2; tm++) {
#pragma unroll
        for (int rh = 0; rh < 2; rh++) {
            const int r = row0 + wm * 32 + tm * 16 + rh * 8 + gid;
            const bool rok = r < NN;
            float s_ = 0.f, d_ = 0.f;
#pragma unroll
            for (int tn = 0; tn < 8; tn++) {
                const int c = wn * 64 + tn * 8 + 2 * tig;
                const float v0 = acc[tm][tn][rh * 2], v1 = acc[tm][tn][rh * 2 + 1];
                s_ = fmaf(v0, att_s[c], fmaf(v1, att_s[c + 1], s_));
                d_ = fmaf(v0, att_d[c], fmaf(v1, att_d[c + 1], d_));
                if (rok)
                    *(__half2*)(g_h + (size_t)r * FD + c) = __floats2half2_rn(v0, v1);
            }
            s_ += __shfl_xor_sync(0xffffffffu, s_, 1);
            s_ += __shfl_xor_sync(0xffffffffu, s_, 2);
            d_ += __shfl_xor_sync(0xffffffffu, d_, 1);
            d_ += __shfl_xor_sync(0xffffffffu, d_, 2);
            if (tig == 0 && rok) {
                g_asrc[r * HEADS + head] = s_;
                g_adst[r * HEADS + head] = d_;
            }
        }
    }
}

// ---------------- per-dst-node aggregation: one warp per node ----------------
// Single pass, max-free softmax (logits O(5): exp cannot overflow).
// fp16 h rows (1 LDG.128/lane/edge) + x4 batched unroll for high MLP.
__global__ void __launch_bounds__(256) k_aggregate(
    const float* __restrict__ bias,
    float* __restrict__ outp)               // nullptr -> g_y
{
    const int w = (blockIdx.x * blockDim.x + threadIdx.x) >> 5;
    const int lane = threadIdx.x & 31;
    if (w >= NN) return;
    const int hd = lane >> 3;
    const float ad = g_adst[w * HEADS + hd];
    const int beg = g_off[w], end = g_off[w + 1];

    // self loop
    float wt = __expf(lrelu(g_asrc[w * HEADS + hd] + ad));
    float denom = wt;
    float a0, a1, a2, a3, a4, a5, a6, a7;
    {
        const uint4 raw = *(const uint4*)(g_h + (size_t)w * FD + lane * 8);
        const __half2* hp = (const __half2*)&raw;
        const float2 f0 = __half22float2(hp[0]), f1 = __half22float2(hp[1]);
        const float2 f2 = __half22float2(hp[2]), f3 = __half22float2(hp[3]);
        a0 = wt * f0.x; a1 = wt * f0.y; a2 = wt * f1.x; a3 = wt * f1.y;
        a4 = wt * f2.x; a5 = wt * f2.y; a6 = wt * f3.x; a7 = wt * f3.y;
    }

    int k = beg;
    for (; k + 4 <= end; k += 4) {
        const int s0 = g_col[k], s1 = g_col[k + 1];
        const int s2 = g_col[k + 2], s3 = g_col[k + 3];
        const float e0 = g_asrc[s0 * HEADS + hd] + ad;
        const float e1 = g_asrc[s1 * HEADS + hd] + ad;
        const float e2 = g_asrc[s2 * HEADS + hd] + ad;
        const float e3 = g_asrc[s3 * HEADS + hd] + ad;
        const uint4 r0 = *(const uint4*)(g_h + (size_t)s0 * FD + lane * 8);
        const uint4 r1 = *(const uint4*)(g_h + (size_t)s1 * FD + lane * 8);
        const uint4 r2 = *(const uint4*)(g_h + (size_t)s2 * FD + lane * 8);
        const uint4 r3 = *(const uint4*)(g_h + (size_t)s3 * FD + lane * 8);
        const float w0 = __expf(lrelu(e0)), w1 = __expf(lrelu(e1));
        const float w2 = __expf(lrelu(e2)), w3 = __expf(lrelu(e3));
        denom += (w0 + w1) + (w2 + w3);
        const __half2* p0 = (const __half2*)&r0;
        const __half2* p1 = (const __half2*)&r1;
        const __half2* p2 = (const __half2*)&r2;
        const __half2* p3 = (const __half2*)&r3;
#define ACC8(pp, ww) { \
        const float2 x0 = __half22float2((pp)[0]), x1 = __half22float2((pp)[1]); \
        const float2 x2 = __half22float2((pp)[2]), x3 = __half22float2((pp)[3]); \
        a0 = fmaf((ww), x0.x, a0); a1 = fmaf((ww), x0.y, a1); \
        a2 = fmaf((ww), x1.x, a2); a3 = fmaf((ww), x1.y, a3); \
        a4 = fmaf((ww), x2.x, a4); a5 = fmaf((ww), x2.y, a5); \
        a6 = fmaf((ww), x3.x, a6); a7 = fmaf((ww), x3.y, a7); }
        ACC8(p0, w0) ACC8(p1, w1) ACC8(p2, w2) ACC8(p3, w3)
    }
    for (; k < end; k++) {
        const int s = g_col[k];
        const float wt1 = __expf(lrelu(g_asrc[s * HEADS + hd] + ad));
        denom += wt1;
        const uint4 raw = *(const uint4*)(g_h + (size_t)s * FD + lane * 8);
        const __half2* hp = (const __half2*)&raw;
        ACC8(hp, wt1)
    }
#undef ACC8

    const float inv = 1.0f / (denom + 1e-16f);
    const float* bp = bias + lane * 8;
    float r0 = a0 * inv + bp[0], r1 = a1 * inv + bp[1];
    float r2 = a2 * inv + bp[2], r3 = a3 * inv + bp[3];
    float r4 = a4 * inv + bp[4], r5 = a5 * inv + bp[5];
    float r6 = a6 * inv + bp[6], r7 = a7 * inv + bp[7];
    r0 = r0 > 0.f ? r0 : expm1f(r0);  r1 = r1 > 0.f ? r1 : expm1f(r1);
    r2 = r2 > 0.f ? r2 : expm1f(r2);  r3 = r3 > 0.f ? r3 : expm1f(r3);
    r4 = r4 > 0.f ? r4 : expm1f(r4);  r5 = r5 > 0.f ? r5 : expm1f(r5);
    r6 = r6 > 0.f ? r6 : expm1f(r6);  r7 = r7 > 0.f ? r7 : expm1f(r7);

    float* op = (outp ? outp : g_y) + (size_t)w * FD + lane * 8;
    *(float4*)op       = make_float4(r0, r1, r2, r3);
    *((float4*)op + 1) = make_float4(r4, r5, r6, r7);
}

// ---------------- launch ----------------
extern "C" void kernel_launch(void* const* d_in, const int* in_sizes, int n_in,
                              void* d_out, int out_size)
{
    const float* x   = (const float*)d_in[0];
    const int*   ei  = (const int*)d_in[1];
    const float* W1  = (const float*)d_in[2];
    const float* as1 = (const float*)d_in[3];
    const float* ad1 = (const float*)d_in[4];
    const float* b1  = (const float*)d_in[5];
    const float* W2  = (const float*)d_in[6];
    const float* as2 = (const float*)d_in[7];
    const float* ad2 = (const float*)d_in[8];
    const float* b2  = (const float*)d_in[9];

    const int* src = ei;            // edge_index row 0
    const int* dst = ei + NE;       // edge_index row 1

    const int ggrid = (NN + 63) / 64;
    const int agrid = (NN * 32 + 255) / 256;

    // CSR build interleaved with layer-1 GEMM: k_gemm_att stays in the
    // profiled (4th) launch slot; gemm1 has no dependence on the CSR.
    k_zero_cnt<<<(NN + 255) / 256, 256>>>();
    k_hist<<<(NE + 255) / 256, 256>>>(dst);
    k_scan<<<1, 1024>>>();                            // scan + re-zero g_cnt
    k_gemm_att<<<ggrid, 256>>>(x, W1, as1, ad1);      // <- profiled slot
    k_scatter<<<(NE + 255) / 256, 256>>>(src, dst);

    // layer 1 aggregation
    k_aggregate<<<agrid, 256>>>(b1, nullptr);
    // layer 2
    k_gemm_att<<<ggrid, 256>>>(nullptr, W2, as2, ad2);
    k_aggregate<<<agrid, 256>>>(b2, (float*)d_out);
}

// round 7
// speedup vs baseline: 1.6158x; 1.0135x over previous
#include <cuda_runtime.h>
#include <cuda_fp16.h>
#include <math.h>

#define NN 50000
#define NE 800000
#define FD 256
#define HEADS 4
#define CH 64

// ---- scratch (static device globals: no runtime allocation) ----
__device__ __half g_h[(size_t)NN * FD];    // GEMM output (fp16: halves gather traffic)
__device__ float  g_y[(size_t)NN * FD];    // layer-1 output (GEMM input of layer 2)
__device__ float  g_asrc[NN * HEADS];
__device__ float  g_adst[NN * HEADS];
__device__ int    g_cnt[NN];
__device__ int    g_off[NN + 1];
__device__ int    g_col[NE];               // CSR: src per position

__device__ __forceinline__ float lrelu(float x) { return fmaxf(x, 0.2f * x); }

__device__ __forceinline__ unsigned f2tf(float f) {
    unsigned u;
    asm("cvt.rna.tf32.f32 %0, %1;" : "=r"(u) : "f"(f));
    return u;
}

__device__ __forceinline__ void mma_tf32(float* c, const unsigned* a, const unsigned* b) {
    asm volatile(
        "mma.sync.aligned.m16n8k8.row.col.f32.tf32.tf32.f32 "
        "{%0,%1,%2,%3},{%4,%5,%6,%7},{%8,%9},{%0,%1,%2,%3};"
        : "+f"(c[0]), "+f"(c[1]), "+f"(c[2]), "+f"(c[3])
        : "r"(a[0]), "r"(a[1]), "r"(a[2]), "r"(a[3]), "r"(b[0]), "r"(b[1]));
}

// ---------------- CSR build ----------------
__global__ void k_zero_cnt() {
    int i = blockIdx.x * blockDim.x + threadIdx.x;
    if (i < NN) g_cnt[i] = 0;
}

__global__ void k_hist(const int* __restrict__ dst) {
    int e = blockIdx.x * blockDim.x + threadIdx.x;
    if (e < NE) atomicAdd(&g_cnt[dst[e]], 1);
}

// single-block shuffle scan: 1024 threads x 49 contiguous counts each.
__global__ void k_scan() {
    const int T = 1024, PER = (NN + T - 1) / T;   // 49
    __shared__ int wsum[32];
    const int t = threadIdx.x, lane = t & 31, wid = t >> 5;
    const int base = t * PER;

    int sum = 0;
    for (int i = 0; i < PER; i++) {
        int idx = base + i;
        if (idx < NN) sum += g_cnt[idx];
    }
    int v = sum;
#pragma unroll
    for (int o = 1; o < 32; o <<= 1) {
        int n = __shfl_up_sync(0xffffffffu, v, o);
        if (lane >= o) v += n;
    }
    if (lane == 31) wsum[wid] = v;
    __syncthreads();
    if (wid == 0) {
        int wv = wsum[lane];
#pragma unroll
        for (int o = 1; o < 32; o <<= 1) {
            int n = __shfl_up_sync(0xffffffffu, wv, o);
            if (lane >= o) wv += n;
        }
        wsum[lane] = wv;
    }
    __syncthreads();
    int run = v - sum + (wid > 0 ? wsum[wid - 1] : 0);
    for (int i = 0; i < PER; i++) {
        int idx = base + i;
        if (idx < NN) {
            int c = g_cnt[idx];
            g_off[idx] = run;
            run += c;
            g_cnt[idx] = 0;
        }
    }
    if (t == 0) g_off[NN] = wsum[31];
}

__global__ void k_scatter(const int* __restrict__ src, const int* __restrict__ dst) {
    int e = blockIdx.x * blockDim.x + threadIdx.x;
    if (e < NE) {
        int d = dst[e];
        int pos = g_off[d] + atomicAdd(&g_cnt[d], 1);
        g_col[pos] = src[e];
    }
}

// ---------------- tf32 tensor-core GEMM + fused attention-logit epilogue ----
// Block tile 128(M) x 256(N), BK=16, 8 warps = 2 wm x 4 wn; WARP TILE 64x64
// (acc = 128 regs): 4 LDS.128 (A) + 16 LDS.32 (B) = 4KB smem reads feed 32
// MMAs -> 125 B/MMA (was 187). Each warp's 64 cols = one head (head = wn).
// A fragment-major: unit16 = kkb*256 + rt*32 + gid*4 + tig (rt = row/16),
// word = rh + 2*kh. Double-buffered smem, register prefetch.
__global__ void __launch_bounds__(256, 1) k_gemm_att(
    const float* __restrict__ Ain,          // nullptr -> use g_y
    const float* __restrict__ W,
    const float* __restrict__ att_s,
    const float* __restrict__ att_d)
{
    const float* A = Ain ? Ain : g_y;
    __shared__ unsigned sAf[2][2048];       // fragment-major A (8KB/stage)
    __shared__ unsigned sB[2][16][264];     // [k][n] stride 264 (conflict-free)

    const int t    = threadIdx.x;
    const int lane = t & 31;
    const int wid  = t >> 5;
    const int gid  = lane >> 2, tig = lane & 3;
    const int wm   = wid & 1,   wn  = wid >> 1;   // rows wm*64, cols wn*64
    const int row0 = blockIdx.x * 128;

    float acc[4][8][4] = {};                // [tm][tn][c]

    // ---- staging indices ----
    const int ar = t >> 1, acb = (t & 1) * 8;     // A: row ar, cols acb..acb+7
    const int br = t >> 4, bc = (t & 15) * 4;     // B: row br, 4x 64-strided float4
    const bool arow_ok = (row0 + ar) < NN;
    const float* aptr = A + (size_t)(row0 + ar) * FD + acb;
    const float* bptr = W + (size_t)br * FD + bc;

    // A store word addresses (loop-invariant): fragment-major layout
    int a_st[8];
    {
        const int rt_s = ar >> 4, rh_s = (ar >> 3) & 1, gid_s = ar & 7;
        const int kkb_s = t & 1;              // acb = kkb_s*8
#pragma unroll
        for (int j = 0; j < 8; j++) {
            const int tg = j & 3, kh = j >> 2;
            a_st[j] = (kkb_s * 256 + rt_s * 32 + gid_s * 4 + tg) * 4
                      + rh_s + 2 * kh;
        }
    }
    const int a_lane = (gid * 4 + tig) * 4;       // lane offset in words
    const int b_rd   = tig * 264 + wn * 64 + gid;

    float4 aval0 = make_float4(0.f, 0.f, 0.f, 0.f), aval1 = aval0;
    float4 bval[4];
    if (arow_ok) { aval0 = *(const float4*)aptr; aval1 = *(const float4*)(aptr + 4); }
#pragma unroll
    for (int sub = 0; sub < 4; sub++)
        bval[sub] = *(const float4*)(bptr + sub * 64);

    int st = 0;
    for (int k0 = 0; k0 < FD; k0 += 16) {
        sAf[st][a_st[0]] = f2tf(aval0.x);
        sAf[st][a_st[1]] = f2tf(aval0.y);
        sAf[st][a_st[2]] = f2tf(aval0.z);
        sAf[st][a_st[3]] = f2tf(aval0.w);
        sAf[st][a_st[4]] = f2tf(aval1.x);
        sAf[st][a_st[5]] = f2tf(aval1.y);
        sAf[st][a_st[6]] = f2tf(aval1.z);
        sAf[st][a_st[7]] = f2tf(aval1.w);
#pragma unroll
        for (int sub = 0; sub < 4; sub++)
            *(uint4*)&sB[st][br][bc + sub * 64] =
                make_uint4(f2tf(bval[sub].x), f2tf(bval[sub].y),
                           f2tf(bval[sub].z), f2tf(bval[sub].w));
        __syncthreads();

        if (k0 + 16 < FD) {                 // prefetch next chunk into regs
            aval0 = make_float4(0.f, 0.f, 0.f, 0.f); aval1 = aval0;
            if (arow_ok) {
                aval0 = *(const float4*)(aptr + k0 + 16);
                aval1 = *(const float4*)(aptr + k0 + 20);
            }
#pragma unroll
            for (int sub = 0; sub < 4; sub++)
                bval[sub] = *(const float4*)(bptr + (size_t)(k0 + 16) * FD + sub * 64);
        }

        const unsigned* sa = sAf[st];
        const unsigned* sb = &sB[st][0][0] + b_rd;
#pragma unroll
        for (int kkb = 0; kkb < 2; kkb++) {
            const unsigned* b0 = sb + kkb * (8 * 264);
            unsigned bf[8][2];
#pragma unroll
            for (int tn = 0; tn < 8; tn++) {
                bf[tn][0] = b0[tn * 8];
                bf[tn][1] = b0[4 * 264 + tn * 8];
            }
            const unsigned* abase = sa + kkb * 1024 + wm * 512 + a_lane;
#pragma unroll
            for (int tm = 0; tm < 4; tm++) {
                const uint4 af = *(const uint4*)(abase + tm * 128);
#pragma unroll
                for (int tn = 0; tn < 8; tn++)
                    mma_tf32(acc[tm][tn], (const unsigned*)&af, bf[tn]);
            }
        }
        st ^= 1;
    }

    // ---- epilogue: store h (fp16), fused per-head attention dots ----
    const int head = wn;
#pragma unroll
    for (int tm = 0; tm < 4; tm++) {
#pragma unroll
        for (int rh = 0; rh < 2; rh++) {
            const int r = row0 + wm * 64 + tm * 16 + rh * 8 + gid;
            const bool rok = r < NN;
            float s_ = 0.f, d_ = 0.f;
#pragma unroll
            for (int tn = 0; tn < 8; tn++) {
                const int c = wn * 64 + tn * 8 + 2 * tig;
                const float v0 = acc[tm][tn][rh * 2], v1 = acc[tm][tn][rh * 2 + 1];
                s_ = fmaf(v0, att_s[c], fmaf(v1, att_s[c + 1], s_));
                d_ = fmaf(v0, att_d[c], fmaf(v1, att_d[c + 1], d_));
                if (rok)
                    *(__half2*)(g_h + (size_t)r * FD + c) = __floats2half2_rn(v0, v1);
            }
            s_ += __shfl_xor_sync(0xffffffffu, s_, 1);
            s_ += __shfl_xor_sync(0xffffffffu, s_, 2);
            d_ += __shfl_xor_sync(0xffffffffu, d_, 1);
            d_ += __shfl_xor_sync(0xffffffffu, d_, 2);
            if (tig == 0 && rok) {
                g_asrc[r * HEADS + head] = s_;
                g_adst[r * HEADS + head] = d_;
            }
        }
    }
}

// ---------------- per-dst-node aggregation: one warp per node ----------------
// Single pass, max-free softmax (logits O(5): exp cannot overflow).
// fp16 h rows (1 LDG.128/lane/edge) + x4 batched unroll for high MLP.
__global__ void __launch_bounds__(256) k_aggregate(
    const float* __restrict__ bias,
    float* __restrict__ outp)               // nullptr -> g_y
{
    const int w = (blockIdx.x * blockDim.x + threadIdx.x) >> 5;
    const int lane = threadIdx.x & 31;
    if (w >= NN) return;
    const int hd = lane >> 3;
    const float ad = g_adst[w * HEADS + hd];
    const int beg = g_off[w], end = g_off[w + 1];

    // self loop
    float wt = __expf(lrelu(g_asrc[w * HEADS + hd] + ad));
    float denom = wt;
    float a0, a1, a2, a3, a4, a5, a6, a7;
    {
        const uint4 raw = *(const uint4*)(g_h + (size_t)w * FD + lane * 8);
        const __half2* hp = (const __half2*)&raw;
        const float2 f0 = __half22float2(hp[0]), f1 = __half22float2(hp[1]);
        const float2 f2 = __half22float2(hp[2]), f3 = __half22float2(hp[3]);
        a0 = wt * f0.x; a1 = wt * f0.y; a2 = wt * f1.x; a3 = wt * f1.y;
        a4 = wt * f2.x; a5 = wt * f2.y; a6 = wt * f3.x; a7 = wt * f3.y;
    }

    int k = beg;
    for (; k + 4 <= end; k += 4) {
        const int s0 = g_col[k], s1 = g_col[k + 1];
        const int s2 = g_col[k + 2], s3 = g_col[k + 3];
        const float e0 = g_asrc[s0 * HEADS + hd] + ad;
        const float e1 = g_asrc[s1 * HEADS + hd] + ad;
        const float e2 = g_asrc[s2 * HEADS + hd] + ad;
        const float e3 = g_asrc[s3 * HEADS + hd] + ad;
        const uint4 r0 = *(const uint4*)(g_h + (size_t)s0 * FD + lane * 8);
        const uint4 r1 = *(const uint4*)(g_h + (size_t)s1 * FD + lane * 8);
        const uint4 r2 = *(const uint4*)(g_h + (size_t)s2 * FD + lane * 8);
        const uint4 r3 = *(const uint4*)(g_h + (size_t)s3 * FD + lane * 8);
        const float w0 = __expf(lrelu(e0)), w1 = __expf(lrelu(e1));
        const float w2 = __expf(lrelu(e2)), w3 = __expf(lrelu(e3));
        denom += (w0 + w1) + (w2 + w3);
        const __half2* p0 = (const __half2*)&r0;
        const __half2* p1 = (const __half2*)&r1;
        const __half2* p2 = (const __half2*)&r2;
        const __half2* p3 = (const __half2*)&r3;
#define ACC8(pp, ww) { \
        const float2 x0 = __half22float2((pp)[0]), x1 = __half22float2((pp)[1]); \
        const float2 x2 = __half22float2((pp)[2]), x3 = __half22float2((pp)[3]); \
        a0 = fmaf((ww), x0.x, a0); a1 = fmaf((ww), x0.y, a1); \
        a2 = fmaf((ww), x1.x, a2); a3 = fmaf((ww), x1.y, a3); \
        a4 = fmaf((ww), x2.x, a4); a5 = fmaf((ww), x2.y, a5); \
        a6 = fmaf((ww), x3.x, a6); a7 = fmaf((ww), x3.y, a7); }
        ACC8(p0, w0) ACC8(p1, w1) ACC8(p2, w2) ACC8(p3, w3)
    }
    for (; k < end; k++) {
        const int s = g_col[k];
        const float wt1 = __expf(lrelu(g_asrc[s * HEADS + hd] + ad));
        denom += wt1;
        const uint4 raw = *(const uint4*)(g_h + (size_t)s * FD + lane * 8);
        const __half2* hp = (const __half2*)&raw;
        ACC8(hp, wt1)
    }
#undef ACC8

    const float inv = 1.0f / (denom + 1e-16f);
    const float* bp = bias + lane * 8;
    float r0 = a0 * inv + bp[0], r1 = a1 * inv + bp[1];
    float r2 = a2 * inv + bp[2], r3 = a3 * inv + bp[3];
    float r4 = a4 * inv + bp[4], r5 = a5 * inv + bp[5];
    float r6 = a6 * inv + bp[6], r7 = a7 * inv + bp[7];
    r0 = r0 > 0.f ? r0 : expm1f(r0);  r1 = r1 > 0.f ? r1 : expm1f(r1);
    r2 = r2 > 0.f ? r2 : expm1f(r2);  r3 = r3 > 0.f ? r3 : expm1f(r3);
    r4 = r4 > 0.f ? r4 : expm1f(r4);  r5 = r5 > 0.f ? r5 : expm1f(r5);
    r6 = r6 > 0.f ? r6 : expm1f(r6);  r7 = r7 > 0.f ? r7 : expm1f(r7);

    float* op = (outp ? outp : g_y) + (size_t)w * FD + lane * 8;
    *(float4*)op       = make_float4(r0, r1, r2, r3);
    *((float4*)op + 1) = make_float4(r4, r5, r6, r7);
}

// ---------------- launch ----------------
extern "C" void kernel_launch(void* const* d_in, const int* in_sizes, int n_in,
                              void* d_out, int out_size)
{
    const float* x   = (const float*)d_in[0];
    const int*   ei  = (const int*)d_in[1];
    const float* W1  = (const float*)d_in[2];
    const float* as1 = (const float*)d_in[3];
    const float* ad1 = (const float*)d_in[4];
    const float* b1  = (const float*)d_in[5];
    const float* W2  = (const float*)d_in[6];
    const float* as2 = (const float*)d_in[7];
    const float* ad2 = (const float*)d_in[8];
    const float* b2  = (const float*)d_in[9];

    const int* src = ei;            // edge_index row 0
    const int* dst = ei + NE;       // edge_index row 1

    const int ggrid = (NN + 127) / 128;
    const int agrid = (NN * 32 + 255) / 256;

    // CSR build interleaved with layer-1 GEMM: k_gemm_att stays in the
    // profiled (4th) launch slot; gemm1 has no dependence on the CSR.
    k_zero_cnt<<<(NN + 255) / 256, 256>>>();
    k_hist<<<(NE + 255) / 256, 256>>>(dst);
    k_scan<<<1, 1024>>>();                            // scan + re-zero g_cnt
    k_gemm_att<<<ggrid, 256>>>(x, W1, as1, ad1);      // <- profiled slot
    k_scatter<<<(NE + 255) / 256, 256>>>(src, dst);

    // layer 1 aggregation
    k_aggregate<<<agrid, 256>>>(b1, nullptr);
    // layer 2
    k_gemm_att<<<ggrid, 256>>>(nullptr, W2, as2, ad2);
    k_aggregate<<<agrid, 256>>>(b2, (float*)d_out);
}